// round 4
// baseline (speedup 1.0000x reference)
#include <cuda_runtime.h>
#include <cstdint>

// LIF neuron scan: x[T=8, B, C, H, W] fp32 -> spikes {-1,0,+1} fp32.
// tau = 5/3; V' = V + (-V/tau + x); spike if |V'| >= 1; hard reset to 0.
//
// R4 = best-of-R2/R3:
//  - scalar Markstein correctly-rounded div-by-const (bit-identical to
//    __fdiv_rn for normal operands): regs back to ~32, full occupancy.
//  - single-FSETP spike logic (|vn| >= 1 via free abs modifier, then
//    copysign + select), vs R2's two compares.
//  - __ldcs/__stcs streaming hints on the zero-reuse 268MB stream.
// Kernel is sustained-HBM-bound; this is the minimal-instruction,
// minimal-register posture against that ceiling.

static constexpr int T_STEPS = 8;

__device__ __forceinline__ void lif_step(float& V, float xv, float& o) {
    constexpr float TAU = 5.0f / 3.0f;        // fl(5/3), matches jnp float32
    constexpr float R   = 1.0f / TAU;         // RN(1/fl(5/3)), compile-time

    // q = RN((-V)/TAU) via Markstein (mul + 2 fma), correctly rounded.
    float a  = -V;
    float q0 = __fmul_rn(a, R);
    float e  = __fmaf_rn(-TAU, q0, a);
    float q  = __fmaf_rn(e, R, q0);

    float dv = __fadd_rn(q, xv);              // dv = -V/tau + x
    float vn = __fadd_rn(V, dv);              // V_new = V + dv

    bool p = fabsf(vn) >= 1.0f;               // one FSETP, |src| free
    o = p ? copysignf(1.0f, vn) : 0.0f;       // LOP3 + FSEL
    V = p ? 0.0f : vn;                        // FSEL
}

__global__ __launch_bounds__(256)
void lif_kernel(const float4* __restrict__ x, float4* __restrict__ y, int n4) {
    int i = blockIdx.x * blockDim.x + threadIdx.x;
    if (i >= n4) return;

    // Batched streaming prefetch: 8 independent LDG.128.CS in flight.
    float4 xs[T_STEPS];
#pragma unroll
    for (int t = 0; t < T_STEPS; ++t)
        xs[t] = __ldcs(&x[t * n4 + i]);

    float4 V = make_float4(0.f, 0.f, 0.f, 0.f);
#pragma unroll
    for (int t = 0; t < T_STEPS; ++t) {
        float4 o;
        lif_step(V.x, xs[t].x, o.x);
        lif_step(V.y, xs[t].y, o.y);
        lif_step(V.z, xs[t].z, o.z);
        lif_step(V.w, xs[t].w, o.w);
        __stcs(&y[t * n4 + i], o);            // STG.128 evict-first
    }
}

extern "C" void kernel_launch(void* const* d_in, const int* in_sizes, int n_in,
                              void* d_out, int out_size) {
    const float* x = (const float*)d_in[0];
    float* y = (float*)d_out;

    int total = in_sizes[0];          // T*B*C*H*W = 33,554,432
    int n_spatial = total / T_STEPS;  // 4,194,304
    int n4 = n_spatial / 4;           // 1,048,576 float4 lanes

    int threads = 256;
    int blocks = (n4 + threads - 1) / threads;
    lif_kernel<<<blocks, threads>>>((const float4*)x, (float4*)y, n4);
}